// round 5
// baseline (speedup 1.0000x reference)
#include <cuda_runtime.h>
#include <cuda_bf16.h>

// Word2Vec SGNS loss, bandwidth/latency optimized:
//   - 16 lanes x float4 = one 256B row per half-warp; each load instruction
//     gathers TWO rows (edge A in lanes 0-15, edge B in lanes 16-31).
//   - 16 edges per warp, fully unrolled -> 16 independent float4 row gathers
//     in flight per warp before any consumer (MLP = 16).
//   - butterfly reduce within 16-lane halves (4 shfls reduce 2 edges at once).
//   - reduction: block partial -> one atomicAdd per block to d_out, which is
//     zeroed by a tiny prologue kernel (proven-safe two-launch structure).

#define THREADS 256
#define WARPS_PER_BLOCK (THREADS / 32)
#define PAIRS 8                      // 2 edges per pair -> 16 edges per warp
#define EDGES_PER_WARP (2 * PAIRS)

__global__ void zero_out_kernel(float* out) {
    out[0] = 0.0f;
}

__global__ __launch_bounds__(THREADS, 2) void sgns_loss_kernel(
    const int* __restrict__ pos_u,
    const int* __restrict__ pos_v,
    const int* __restrict__ neg_u,
    const int* __restrict__ neg_v,
    const float* __restrict__ u_emb,
    const float* __restrict__ v_emb,
    float* __restrict__ out,
    int B,
    int total)   // B * (K + 1)
{
    const int warp_in_block = threadIdx.x >> 5;
    const int lane = threadIdx.x & 31;
    const int half = lane >> 4;          // which edge of the pair this lane serves
    const int l16 = lane & 15;           // lane within the 16-lane row group
    const long long warp = (long long)blockIdx.x * WARPS_PER_BLOCK + warp_in_block;
    const long long base = warp * EDGES_PER_WARP;

    int ui[PAIRS], vi[PAIRS];
    bool valid[PAIRS];

    // Phase 1: index gathers (broadcast loads, L1/L2-resident)
    #pragma unroll
    for (int p = 0; p < PAIRS; p++) {
        long long e = base + 2 * p + half;
        valid[p] = (e < total);
        long long es = valid[p] ? e : 0;
        if (es < B) {
            ui[p] = __ldg(pos_u + es);
            vi[p] = __ldg(pos_v + es);
        } else {
            long long t = es - B;
            ui[p] = __ldg(neg_u + t);
            vi[p] = __ldg(neg_v + t);
        }
    }

    // Phase 2: 16 independent 256B row gathers in flight (MLP = 16)
    float4 a[PAIRS], b[PAIRS];
    #pragma unroll
    for (int p = 0; p < PAIRS; p++) {
        a[p] = __ldg(reinterpret_cast<const float4*>(
                   u_emb + (size_t)ui[p] * 64) + l16);
        b[p] = __ldg(reinterpret_cast<const float4*>(
                   v_emb + (size_t)vi[p] * 64) + l16);
    }

    // Phase 3: partial dots + 16-lane butterfly (reduces both halves' edges
    // simultaneously), then stable -logsigmoid on all lanes (SIMD-redundant)
    float loss = 0.0f;
    #pragma unroll
    for (int p = 0; p < PAIRS; p++) {
        float dot = a[p].x * b[p].x + a[p].y * b[p].y
                  + a[p].z * b[p].z + a[p].w * b[p].w;
        #pragma unroll
        for (int off = 8; off > 0; off >>= 1)
            dot += __shfl_xor_sync(0xFFFFFFFFu, dot, off);

        float l = fmaxf(-dot, 0.0f) + log1pf(expf(-fabsf(dot)));
        loss += valid[p] ? l : 0.0f;
    }

    // Combine the two halves; every lane then holds this warp's total.
    loss += __shfl_xor_sync(0xFFFFFFFFu, loss, 16);

    __shared__ float smem[WARPS_PER_BLOCK];
    if (lane == 0) smem[warp_in_block] = loss;
    __syncthreads();

    if (warp_in_block == 0 && lane == 0) {
        float v = 0.0f;
        #pragma unroll
        for (int w = 0; w < WARPS_PER_BLOCK; w++) v += smem[w];
        atomicAdd(out, v);
    }
}

extern "C" void kernel_launch(void* const* d_in, const int* in_sizes, int n_in,
                              void* d_out, int out_size) {
    const int* pos_u = (const int*)d_in[0];
    const int* pos_v = (const int*)d_in[1];
    const int* neg_u = (const int*)d_in[2];
    const int* neg_v = (const int*)d_in[3];
    const float* u_emb = (const float*)d_in[4];
    const float* v_emb = (const float*)d_in[5];
    float* out = (float*)d_out;

    const int B = in_sizes[0];          // 16384
    const int BK = in_sizes[2];         // B * K
    const int total = B + BK;           // B * (K + 1)

    zero_out_kernel<<<1, 1>>>(out);

    const int edges_per_block = WARPS_PER_BLOCK * EDGES_PER_WARP;
    const int blocks = (total + edges_per_block - 1) / edges_per_block;
    sgns_loss_kernel<<<blocks, THREADS>>>(pos_u, pos_v, neg_u, neg_v,
                                          u_emb, v_emb, out, B, total);
}

// round 6
// speedup vs baseline: 1.0576x; 1.0576x over previous
#include <cuda_runtime.h>
#include <cuda_bf16.h>

// Word2Vec SGNS loss, bandwidth/latency optimized:
//   - 16 lanes x float4 = one 256B row per half-warp; each load instruction
//     gathers TWO rows (edge A in lanes 0-15, edge B in lanes 16-31).
//   - 12 edges per warp (PAIRS=6): balances per-warp MLP against register
//     pressure/occupancy (PAIRS=8 @ 54 regs serialized loads and halved occ).
//   - all index math in 32-bit (total edges = 344064 << 2^31) to cut IMAD
//     chains (ALU was ~40% busy) and registers.
//   - butterfly reduce within 16-lane halves (4 shfls reduce 2 edges at once).
//   - reduction: one atomicAdd per block to d_out, zeroed by tiny prologue.

#define THREADS 256
#define WARPS_PER_BLOCK (THREADS / 32)
#define PAIRS 6                      // 2 edges per pair -> 12 edges per warp
#define EDGES_PER_WARP (2 * PAIRS)

__global__ void zero_out_kernel(float* out) {
    out[0] = 0.0f;
}

__global__ __launch_bounds__(THREADS) void sgns_loss_kernel(
    const int* __restrict__ pos_u,
    const int* __restrict__ pos_v,
    const int* __restrict__ neg_u,
    const int* __restrict__ neg_v,
    const float* __restrict__ u_emb,
    const float* __restrict__ v_emb,
    float* __restrict__ out,
    int B,
    int total)   // B * (K + 1)
{
    const int warp_in_block = threadIdx.x >> 5;
    const int lane = threadIdx.x & 31;
    const int half = lane >> 4;          // which edge of the pair this lane serves
    const int l16 = lane & 15;           // lane within the 16-lane row group
    const int warp = blockIdx.x * WARPS_PER_BLOCK + warp_in_block;
    const int base = warp * EDGES_PER_WARP;

    int ui[PAIRS], vi[PAIRS];
    bool valid[PAIRS];

    // Phase 1: index gathers (broadcast loads, L1/L2-resident)
    #pragma unroll
    for (int p = 0; p < PAIRS; p++) {
        int e = base + 2 * p + half;
        valid[p] = (e < total);
        int es = valid[p] ? e : 0;
        if (es < B) {
            ui[p] = __ldg(pos_u + es);
            vi[p] = __ldg(pos_v + es);
        } else {
            int t = es - B;
            ui[p] = __ldg(neg_u + t);
            vi[p] = __ldg(neg_v + t);
        }
    }

    // Phase 2: 12 independent 256B row gathers in flight
    float4 a[PAIRS], b[PAIRS];
    #pragma unroll
    for (int p = 0; p < PAIRS; p++) {
        a[p] = __ldg(reinterpret_cast<const float4*>(
                   u_emb + (size_t)((unsigned)ui[p]) * 64) + l16);
        b[p] = __ldg(reinterpret_cast<const float4*>(
                   v_emb + (size_t)((unsigned)vi[p]) * 64) + l16);
    }

    // Phase 3: partial dots + 16-lane butterfly (reduces both halves' edges
    // simultaneously), then stable -logsigmoid on all lanes (SIMD-redundant)
    float loss = 0.0f;
    #pragma unroll
    for (int p = 0; p < PAIRS; p++) {
        float dot = a[p].x * b[p].x + a[p].y * b[p].y
                  + a[p].z * b[p].z + a[p].w * b[p].w;
        #pragma unroll
        for (int off = 8; off > 0; off >>= 1)
            dot += __shfl_xor_sync(0xFFFFFFFFu, dot, off);

        float l = fmaxf(-dot, 0.0f) + log1pf(expf(-fabsf(dot)));
        loss += valid[p] ? l : 0.0f;
    }

    // Combine the two halves; every lane then holds this warp's total.
    loss += __shfl_xor_sync(0xFFFFFFFFu, loss, 16);

    __shared__ float smem[WARPS_PER_BLOCK];
    if (lane == 0) smem[warp_in_block] = loss;
    __syncthreads();

    if (warp_in_block == 0 && lane == 0) {
        float v = 0.0f;
        #pragma unroll
        for (int w = 0; w < WARPS_PER_BLOCK; w++) v += smem[w];
        atomicAdd(out, v);
    }
}

extern "C" void kernel_launch(void* const* d_in, const int* in_sizes, int n_in,
                              void* d_out, int out_size) {
    const int* pos_u = (const int*)d_in[0];
    const int* pos_v = (const int*)d_in[1];
    const int* neg_u = (const int*)d_in[2];
    const int* neg_v = (const int*)d_in[3];
    const float* u_emb = (const float*)d_in[4];
    const float* v_emb = (const float*)d_in[5];
    float* out = (float*)d_out;

    const int B = in_sizes[0];          // 16384
    const int BK = in_sizes[2];         // B * K
    const int total = B + BK;           // B * (K + 1)

    zero_out_kernel<<<1, 1>>>(out);

    const int edges_per_block = WARPS_PER_BLOCK * EDGES_PER_WARP;
    const int blocks = (total + edges_per_block - 1) / edges_per_block;
    sgns_loss_kernel<<<blocks, THREADS>>>(pos_u, pos_v, neg_u, neg_v,
                                          u_emb, v_emb, out, B, total);
}

// round 7
// speedup vs baseline: 1.2029x; 1.1374x over previous
#include <cuda_runtime.h>
#include <cuda_bf16.h>
#include <cstdint>

// Word2Vec SGNS loss — cp.async (LDGSTS) staging version.
// Register-file analysis (R2 vs R5/R6): per-warp MLP through registers caps
// at 8 rows (32 regs). cp.async global->shared holds 32 rows (16 edges) in
// flight per warp with ~32 regs, keeping occupancy at ~88% while doubling
// SM-wide outstanding memory requests.
//
//   - lanes 0-15 stage u-rows, lanes 16-31 stage v-rows; one cp.async
//     instruction moves 2 coalesced 256B rows (same pattern as the LDG.128
//     kernel, 16B per lane).
//   - each lane owns one edge index; per-iteration shfl broadcasts it.
//   - compute: conflict-free LDS.128 + 16-lane butterfly (2 edges at once).

#define THREADS 128
#define WPB (THREADS / 32)     // 4 warps / block
#define EPW 16                 // edges per warp
#define PAIRS (EPW / 2)

__global__ void zero_out_kernel(float* out) {
    out[0] = 0.0f;
}

__device__ __forceinline__ void cp_async16(uint32_t dst_smem, const void* src) {
    asm volatile("cp.async.cg.shared.global [%0], [%1], 16;\n"
                 :: "r"(dst_smem), "l"(src));
}

__global__ __launch_bounds__(THREADS) void sgns_loss_kernel(
    const int* __restrict__ pos_u,
    const int* __restrict__ pos_v,
    const int* __restrict__ neg_u,
    const int* __restrict__ neg_v,
    const float* __restrict__ u_emb,
    const float* __restrict__ v_emb,
    float* __restrict__ out,
    int B,
    int total)   // B * (K + 1)
{
    __shared__ float buf[WPB][EPW][2][64];   // 32 KB staging
    __shared__ float warp_part[WPB];

    const int w = threadIdx.x >> 5;
    const int lane = threadIdx.x & 31;
    const int half = lane >> 4;          // 0: u-table, 1: v-table
    const int l16 = lane & 15;
    const int warp_g = blockIdx.x * WPB + w;
    const int base = warp_g * EPW;

    // Each lane owns the index for edge l16 in its table.
    int eown = base + l16;
    int es = (eown < total) ? eown : 0;
    int myidx;
    if (half == 0)
        myidx = (es < B) ? __ldg(pos_u + es) : __ldg(neg_u + (es - B));
    else
        myidx = (es < B) ? __ldg(pos_v + es) : __ldg(neg_v + (es - B));

    const float* __restrict__ tab = half ? v_emb : u_emb;

    // Stage 16 edges x 2 rows into smem; all 16 cp.asyncs independent.
    #pragma unroll
    for (int t = 0; t < EPW; t++) {
        int idx = __shfl_sync(0xFFFFFFFFu, myidx, (lane & 16) + t);
        const float* src = tab + (size_t)(unsigned)idx * 64 + l16 * 4;
        uint32_t dst = (uint32_t)__cvta_generic_to_shared(&buf[w][t][half][l16 * 4]);
        cp_async16(dst, src);
    }
    asm volatile("cp.async.commit_group;\n" ::: "memory");
    asm volatile("cp.async.wait_group 0;\n" ::: "memory");
    __syncwarp();

    // Consume: pair p -> lanes 0-15 do edge 2p, lanes 16-31 edge 2p+1.
    float loss = 0.0f;
    #pragma unroll
    for (int p = 0; p < PAIRS; p++) {
        int e = 2 * p + half;
        float4 a = *reinterpret_cast<const float4*>(&buf[w][e][0][l16 * 4]);
        float4 b = *reinterpret_cast<const float4*>(&buf[w][e][1][l16 * 4]);
        float dot = a.x * b.x + a.y * b.y + a.z * b.z + a.w * b.w;
        #pragma unroll
        for (int off = 8; off > 0; off >>= 1)
            dot += __shfl_xor_sync(0xFFFFFFFFu, dot, off);

        float l = fmaxf(-dot, 0.0f) + log1pf(expf(-fabsf(dot)));
        loss += ((base + e) < total) ? l : 0.0f;
    }

    // Combine halves; every lane then holds this warp's total.
    loss += __shfl_xor_sync(0xFFFFFFFFu, loss, 16);

    if (lane == 0) warp_part[w] = loss;
    __syncthreads();

    if (threadIdx.x == 0) {
        float v = 0.0f;
        #pragma unroll
        for (int i = 0; i < WPB; i++) v += warp_part[i];
        atomicAdd(out, v);
    }
}

extern "C" void kernel_launch(void* const* d_in, const int* in_sizes, int n_in,
                              void* d_out, int out_size) {
    const int* pos_u = (const int*)d_in[0];
    const int* pos_v = (const int*)d_in[1];
    const int* neg_u = (const int*)d_in[2];
    const int* neg_v = (const int*)d_in[3];
    const float* u_emb = (const float*)d_in[4];
    const float* v_emb = (const float*)d_in[5];
    float* out = (float*)d_out;

    const int B = in_sizes[0];          // 16384
    const int BK = in_sizes[2];         // B * K
    const int total = B + BK;           // B * (K + 1)

    zero_out_kernel<<<1, 1>>>(out);

    const int edges_per_block = WPB * EPW;
    const int blocks = (total + edges_per_block - 1) / edges_per_block;
    sgns_loss_kernel<<<blocks, THREADS>>>(pos_u, pos_v, neg_u, neg_v,
                                          u_emb, v_emb, out, B, total);
}